// round 11
// baseline (speedup 1.0000x reference)
#include <cuda_runtime.h>
#include <cuda_fp16.h>
#include <math.h>
#include <stdint.h>

// Recognition_RNN via fp16 mma.sync GEMMs (sm_103 target: no tcgen05).
//   GEMM1: h_new = tanh([x,h] @ W1^T + b1)  M=8192 N=2048 K=2304   1-term fp16
//   GEMM2: out = h_new @ W2^T + b2          M=8192 N=256  K=2048   1-term fp16
// R11: A-concat+fp32->fp16 conversion fused into g1's load path (prepass = W only);
//      g2 restored to proven R8 2-stage; rel_err must stay 4.199e-4 exactly.

#define B_DIM 8192
#define OBS   256
#define NHD   2048
#define LATD  128
#define KK1   (OBS + NHD)   // 2304
#define KK2   NHD           // 2048
#define NN1   NHD           // 2048
#define NN2   (2 * LATD)    // 256

// ---------------- scratch (fp16 copies) ----------------
__device__ __align__(1024) __half g_W1hi[(size_t)NN1 * KK1];
__device__ __align__(1024) __half g_Hhi[(size_t)B_DIM * KK2];
__device__ __align__(1024) __half g_W2hi[(size_t)NN2 * KK2];

// ---------------- PTX helpers ----------------
__device__ __forceinline__ uint32_t smem_u32(const void* p) {
    uint32_t a;
    asm("{ .reg .u64 t; cvta.to.shared.u64 t, %1; cvt.u32.u64 %0, t; }" : "=r"(a) : "l"(p));
    return a;
}
__device__ __forceinline__ void cp16(uint32_t s, const void* g) {
    asm volatile("cp.async.cg.shared.global [%0], [%1], 16;" :: "r"(s), "l"(g));
}
__device__ __forceinline__ void cp_commit() { asm volatile("cp.async.commit_group;" ::: "memory"); }
__device__ __forceinline__ void cp_wait1()  { asm volatile("cp.async.wait_group 1;" ::: "memory"); }
__device__ __forceinline__ void cp_wait0()  { asm volatile("cp.async.wait_group 0;" ::: "memory"); }

__device__ __forceinline__ void ldsm_x4(uint32_t& r0, uint32_t& r1, uint32_t& r2, uint32_t& r3,
                                        uint32_t addr) {
    asm volatile("ldmatrix.sync.aligned.m8n8.x4.shared.b16 {%0,%1,%2,%3}, [%4];"
                 : "=r"(r0), "=r"(r1), "=r"(r2), "=r"(r3) : "r"(addr));
}
__device__ __forceinline__ void mma_fp16(float* c, const uint32_t* a, const uint32_t* b) {
    asm volatile(
        "mma.sync.aligned.m16n8k16.row.col.f32.f16.f16.f32 "
        "{%0,%1,%2,%3}, {%4,%5,%6,%7}, {%8,%9}, {%0,%1,%2,%3};"
        : "+f"(c[0]), "+f"(c[1]), "+f"(c[2]), "+f"(c[3])
        : "r"(a[0]), "r"(a[1]), "r"(a[2]), "r"(a[3]), "r"(b[0]), "r"(b[1]));
}
__device__ __forceinline__ void sts128(uint32_t addr, uint32_t a, uint32_t b, uint32_t c, uint32_t d) {
    asm volatile("st.shared.v4.b32 [%0], {%1,%2,%3,%4};"
                 :: "r"(addr), "r"(a), "r"(b), "r"(c), "r"(d) : "memory");
}
__device__ __forceinline__ uint32_t swz(uint32_t off) { return off ^ ((off >> 3) & 0x70); }
__device__ __forceinline__ uint32_t h2u(__half2 v) { return *(uint32_t*)&v; }

// ---------------- prepass: W1 + W2 fp32 -> fp16, MLP=4 ----------------
__device__ __forceinline__ void hi_store4(__half* hp, float4 v) {
    union { __half b[4]; uint2 u; } H;
    H.b[0] = __float2half_rn(v.x); H.b[1] = __float2half_rn(v.y);
    H.b[2] = __float2half_rn(v.z); H.b[3] = __float2half_rn(v.w);
    *(uint2*)hp = H.u;
}

#define N_W1  ((uint32_t)((size_t)NN1 * KK1 / 4))     // 1,179,648
#define N_W2  ((uint32_t)((size_t)NN2 * KK2 / 4))     //   131,072
#define N_WT  (N_W1 + N_W2)                           // 1,310,720
#define PRE_ILP 4

__global__ void k_prepass(const float* __restrict__ W1, const float* __restrict__ W2) {
    const uint32_t i0 = blockIdx.x * blockDim.x + threadIdx.x;
    const uint32_t S  = gridDim.x * blockDim.x;

    float4 v[PRE_ILP];
    uint32_t idx[PRE_ILP];
#pragma unroll
    for (int it = 0; it < PRE_ILP; ++it) {
        uint32_t i = i0 + (uint32_t)it * S;
        idx[it] = i;
        if (i < N_W1)       v[it] = *(const float4*)(W1 + (size_t)i * 4);
        else if (i < N_WT)  v[it] = *(const float4*)(W2 + (size_t)(i - N_W1) * 4);
    }
#pragma unroll
    for (int it = 0; it < PRE_ILP; ++it) {
        uint32_t i = idx[it];
        if (i < N_W1)       hi_store4(g_W1hi + (size_t)i * 4, v[it]);
        else if (i < N_WT)  hi_store4(g_W2hi + (size_t)(i - N_W1) * 4, v[it]);
    }
}

// ---------------- tile loader: ROWS x 128B fp16, SW128 swizzled, cp.async ----------------
template<int ROWS, int NTHR>
__device__ __forceinline__ void load_tile(uint32_t sdst, const __half* __restrict__ g,
                                          size_t row0, int ld, int kc, int tid) {
#pragma unroll
    for (int i = 0; i < ROWS * 8 / NTHR; ++i) {
        int op = i * NTHR + tid;
        int r = op >> 3;
        int c = (op & 7) << 4;
        const char* gp = (const char*)(g + (row0 + r) * (size_t)ld + kc) + c;
        cp16(sdst + swz((uint32_t)(r * 128 + c)), gp);
    }
}

// ---------------- fused A loader: fp32 (x|h) -> cvt -> swizzled fp16 STS ----------------
// 256 threads: thread owns row r = tid>>1, 32-col half hh = tid&1 of the 128x64 tile.
// 2 batches of 4 LDG.128 (16 transient regs) -> 4 half2-packed STS.128 total.
__device__ __forceinline__ void load_a_f32(uint32_t sdst, const float* __restrict__ x,
                                           const float* __restrict__ h,
                                           size_t m0, int kc, int tid) {
    const int r  = tid >> 1;
    const int hh = tid & 1;
    const float* src;
    if (kc < OBS) src = x + (m0 + r) * (size_t)OBS + kc + hh * 32;
    else          src = h + (m0 + r) * (size_t)NHD + (kc - OBS) + hh * 32;
    const uint32_t base = (uint32_t)(r * 128 + hh * 64);
#pragma unroll
    for (int b = 0; b < 2; ++b) {
        float4 v0 = *(const float4*)(src + b * 16 + 0);
        float4 v1 = *(const float4*)(src + b * 16 + 4);
        float4 v2 = *(const float4*)(src + b * 16 + 8);
        float4 v3 = *(const float4*)(src + b * 16 + 12);
        sts128(sdst + swz(base + b * 32),
               h2u(__floats2half2_rn(v0.x, v0.y)), h2u(__floats2half2_rn(v0.z, v0.w)),
               h2u(__floats2half2_rn(v1.x, v1.y)), h2u(__floats2half2_rn(v1.z, v1.w)));
        sts128(sdst + swz(base + b * 32 + 16),
               h2u(__floats2half2_rn(v2.x, v2.y)), h2u(__floats2half2_rn(v2.z, v2.w)),
               h2u(__floats2half2_rn(v3.x, v3.y)), h2u(__floats2half2_rn(v3.z, v3.w)));
    }
}

// ================= GEMM1: 1-term, CTA 128x128, 8 warps (32x64 each), 3-stage =================
// stage = A@0 (16K) + B@16K (16K) = 32KB; 3 stages = 96KB; 2 CTAs/SM
// A: fused fp32->fp16 manual path; B: cp.async (groups contain B only).
__global__ __launch_bounds__(256, 2)
void g1_gemm(const float* __restrict__ x, const float* __restrict__ h,
             const float* __restrict__ bias, float* __restrict__ C) {
    constexpr int NTILES = KK1 / 64;   // 36
    constexpr int STAGE  = 32768;

    extern __shared__ unsigned char smem[];
    const uint32_t sb0 = smem_u32(smem);

    const int tid  = threadIdx.x;
    const int lane = tid & 31;
    const int wid  = tid >> 5;
    const int wm   = wid & 3;    // 4 warps along M -> 32 rows each
    const int wn   = wid >> 2;   // 2 warps along N -> 64 cols each
    const size_t m0 = (size_t)blockIdx.y * 128;
    const size_t n0 = (size_t)blockIdx.x * 128;

    float acc[2][8][4];
#pragma unroll
    for (int mt = 0; mt < 2; ++mt)
#pragma unroll
        for (int nt = 0; nt < 8; ++nt)
#pragma unroll
            for (int j = 0; j < 4; ++j) acc[mt][nt][j] = 0.0f;

    const uint32_t a_off0 = (uint32_t)((wm * 32 + (lane & 15)) * 128 + (lane >> 4) * 16);
    const uint32_t b_off0 = (uint32_t)((wn * 64 + (lane & 15)) * 128 + (lane >> 4) * 16);
    uint32_t asw[2], bsw[4];
#pragma unroll
    for (int mt = 0; mt < 2; ++mt) asw[mt] = swz(a_off0 + mt * 2048);
#pragma unroll
    for (int p = 0; p < 4; ++p) bsw[p] = swz(b_off0 + p * 2048);

    // prologue: stages 0,1 (B async; A manual convert-store)
#pragma unroll
    for (int s = 0; s < 2; ++s) {
        uint32_t sb = sb0 + s * STAGE;
        load_tile<128, 256>(sb + 16384, g_W1hi, n0, KK1, s * 64, tid);
        cp_commit();
        load_a_f32(sb, x, h, m0, s * 64, tid);
    }

    int sc = 0, sl = 2;
    for (int t = 0; t < NTILES; ++t) {
        cp_wait1();
        __syncthreads();

        // issue loads for t+2 into buffer finished two tiles ago
        if (t + 2 < NTILES) {
            uint32_t lb = sb0 + sl * STAGE;
            int kc = (t + 2) * 64;
            load_tile<128, 256>(lb + 16384, g_W1hi, n0, KK1, kc, tid);
            cp_commit();
            load_a_f32(lb, x, h, m0, kc, tid);
        } else {
            cp_commit();   // keep group count in lockstep
        }

        const uint32_t sbA = sb0 + sc * STAGE;
        const uint32_t sbB = sbA + 16384;
#pragma unroll
        for (int ks = 0; ks < 4; ++ks) {
            const uint32_t kb = (uint32_t)(ks * 32);
            uint32_t ah[2][4];
#pragma unroll
            for (int mt = 0; mt < 2; ++mt)
                ldsm_x4(ah[mt][0], ah[mt][1], ah[mt][2], ah[mt][3], sbA + (asw[mt] ^ kb));
            uint32_t bh[8][2];
#pragma unroll
            for (int p = 0; p < 4; ++p) {
                uint32_t r0, r1, r2, r3;
                ldsm_x4(r0, r1, r2, r3, sbB + (bsw[p] ^ kb));
                bh[p * 2][0] = r0; bh[p * 2][1] = r2;
                bh[p * 2 + 1][0] = r1; bh[p * 2 + 1][1] = r3;
            }
#pragma unroll
            for (int mt = 0; mt < 2; ++mt)
#pragma unroll
                for (int nt = 0; nt < 8; ++nt)
                    mma_fp16(acc[mt][nt], ah[mt], bh[nt]);
        }
        sc = (sc == 2) ? 0 : sc + 1;
        sl = (sl == 2) ? 0 : sl + 1;
    }

    // epilogue: bias + tanh + fp32 store + fp16 copy for GEMM2
#pragma unroll
    for (int mt = 0; mt < 2; ++mt) {
        const size_t gr0 = m0 + wm * 32 + mt * 16 + (lane >> 2);
#pragma unroll
        for (int nt = 0; nt < 8; ++nt) {
            const size_t n = n0 + wn * 64 + nt * 8 + (lane & 3) * 2;
            const float bv0 = bias[n], bv1 = bias[n + 1];
#pragma unroll
            for (int hlf = 0; hlf < 2; ++hlf) {
                const size_t r = gr0 + hlf * 8;
                float v0 = tanhf(acc[mt][nt][hlf * 2 + 0] + bv0);
                float v1 = tanhf(acc[mt][nt][hlf * 2 + 1] + bv1);
                *(float2*)(C + r * (size_t)NN1 + n) = make_float2(v0, v1);
                union { __half b[2]; uint32_t u; } Hp;
                Hp.b[0] = __float2half_rn(v0);
                Hp.b[1] = __float2half_rn(v1);
                *(uint32_t*)(g_Hhi + r * (size_t)KK2 + n) = Hp.u;
            }
        }
    }
}

// ================= GEMM2: 1-term, CTA 128x64, 8 warps (32x32 each), 2-stage (R8 proven) =========
// stage = Hhi@0 (16K) + W2hi@16K (8K) = 24KB; 2 stages = 48KB; 2 CTAs/SM
__global__ __launch_bounds__(256, 2)
void g2_gemm(const float* __restrict__ bias, float* __restrict__ C) {
    constexpr int NTILES = KK2 / 64;   // 32
    constexpr int STAGE  = 24576;

    extern __shared__ unsigned char smem[];
    const uint32_t sb0 = smem_u32(smem);

    const int tid  = threadIdx.x;
    const int lane = tid & 31;
    const int wid  = tid >> 5;
    const int wm   = wid & 3;    // 4 warps along M -> 32 rows each
    const int wn   = wid >> 2;   // 2 warps along N -> 32 cols each
    const size_t m0 = (size_t)blockIdx.y * 128;
    const size_t n0 = (size_t)blockIdx.x * 64;

    float acc[2][4][4];
#pragma unroll
    for (int mt = 0; mt < 2; ++mt)
#pragma unroll
        for (int nt = 0; nt < 4; ++nt)
#pragma unroll
            for (int j = 0; j < 4; ++j) acc[mt][nt][j] = 0.0f;

    const uint32_t a_off0 = (uint32_t)((wm * 32 + (lane & 15)) * 128 + (lane >> 4) * 16);
    const uint32_t b_off0 = (uint32_t)((wn * 32 + (lane & 15)) * 128 + (lane >> 4) * 16);
    uint32_t asw[2], bsw[2];
#pragma unroll
    for (int mt = 0; mt < 2; ++mt) asw[mt] = swz(a_off0 + mt * 2048);
#pragma unroll
    for (int p = 0; p < 2; ++p) bsw[p] = swz(b_off0 + p * 2048);

#pragma unroll
    for (int s = 0; s < 2; ++s) {
        uint32_t sb = sb0 + s * STAGE;
        int kc = s * 64;
        load_tile<128, 256>(sb,         g_Hhi,  m0, KK2, kc, tid);
        load_tile<64,  256>(sb + 16384, g_W2hi, n0, KK2, kc, tid);
        cp_commit();
    }

    for (int t = 0; t < NTILES; ++t) {
        if (t + 1 < NTILES) cp_wait1(); else cp_wait0();
        __syncthreads();

        const uint32_t sb = sb0 + (t & 1) * STAGE;
#pragma unroll
        for (int ks = 0; ks < 4; ++ks) {
            const uint32_t kb = (uint32_t)(ks * 32);
            uint32_t ah[2][4];
#pragma unroll
            for (int mt = 0; mt < 2; ++mt)
                ldsm_x4(ah[mt][0], ah[mt][1], ah[mt][2], ah[mt][3], sb + (asw[mt] ^ kb));
            uint32_t bh[4][2];
#pragma unroll
            for (int p = 0; p < 2; ++p) {
                uint32_t r0, r1, r2, r3;
                ldsm_x4(r0, r1, r2, r3, sb + 16384 + (bsw[p] ^ kb));
                bh[p * 2][0] = r0; bh[p * 2][1] = r2;
                bh[p * 2 + 1][0] = r1; bh[p * 2 + 1][1] = r3;
            }
#pragma unroll
            for (int mt = 0; mt < 2; ++mt)
#pragma unroll
                for (int nt = 0; nt < 4; ++nt)
                    mma_fp16(acc[mt][nt], ah[mt], bh[nt]);
        }
        __syncthreads();

        if (t + 2 < NTILES) {
            uint32_t lb = sb0 + (t & 1) * STAGE;
            int kc = (t + 2) * 64;
            load_tile<128, 256>(lb,         g_Hhi,  m0, KK2, kc, tid);
            load_tile<64,  256>(lb + 16384, g_W2hi, n0, KK2, kc, tid);
        }
        cp_commit();
    }

#pragma unroll
    for (int mt = 0; mt < 2; ++mt) {
        const size_t gr0 = m0 + wm * 32 + mt * 16 + (lane >> 2);
#pragma unroll
        for (int nt = 0; nt < 4; ++nt) {
            const size_t n = n0 + wn * 32 + nt * 8 + (lane & 3) * 2;
            const float bv0 = bias[n], bv1 = bias[n + 1];
#pragma unroll
            for (int hlf = 0; hlf < 2; ++hlf) {
                const size_t r = gr0 + hlf * 8;
                float v0 = acc[mt][nt][hlf * 2 + 0] + bv0;
                float v1 = acc[mt][nt][hlf * 2 + 1] + bv1;
                *(float2*)(C + r * (size_t)NN2 + n) = make_float2(v0, v1);
            }
        }
    }
}

// ---------------- launch ----------------
extern "C" void kernel_launch(void* const* d_in, const int* in_sizes, int n_in,
                              void* d_out, int out_size) {
    const float* x  = (const float*)d_in[0];
    const float* h  = (const float*)d_in[1];
    const float* W1 = (const float*)d_in[2];
    const float* b1 = (const float*)d_in[3];
    const float* W2 = (const float*)d_in[4];
    const float* b2 = (const float*)d_in[5];

    float* out  = (float*)d_out;                 // [8192, 256]
    float* hnew = out + (size_t)B_DIM * NN2;     // [8192, 2048]

    const int SMEM1 = 3 * 32768;  // 96 KB -> 2 CTAs/SM
    const int SMEM2 = 2 * 24576;  // 48 KB -> 2 CTAs/SM
    cudaFuncSetAttribute(g1_gemm, cudaFuncAttributeMaxDynamicSharedMemorySize, SMEM1);
    cudaFuncSetAttribute(g2_gemm, cudaFuncAttributeMaxDynamicSharedMemorySize, SMEM2);

    const unsigned preBlocks = (N_WT + 256 * PRE_ILP - 1) / (256 * PRE_ILP);
    k_prepass<<<preBlocks, 256>>>(W1, W2);

    g1_gemm<<<dim3(NN1 / 128, B_DIM / 128), 256, SMEM1>>>(x, h, b1, hnew);
    g2_gemm<<<dim3(NN2 / 64,  B_DIM / 128), 256, SMEM2>>>(b2, out);
}

// round 12
// speedup vs baseline: 1.9262x; 1.9262x over previous
#include <cuda_runtime.h>
#include <cuda_fp16.h>
#include <math.h>
#include <stdint.h>

// Recognition_RNN via fp16 mma.sync GEMMs (sm_103 target: no tcgen05).
//   GEMM1: h_new = tanh([x,h] @ W1^T + b1)  M=8192 N=2048 K=2304   1-term fp16
//   GEMM2: out = h_new @ W2^T + b2          M=8192 N=256  K=2048   1-term fp16
// R12 (final consolidation): R8 g1 (3-stage 128x128) + R8 g2 (2-stage 128x64)
//   + R9 u32-div MLP-4 prepass. All components individually proven fastest.

#define B_DIM 8192
#define OBS   256
#define NHD   2048
#define LATD  128
#define KK1   (OBS + NHD)   // 2304
#define KK2   NHD           // 2048
#define NN1   NHD           // 2048
#define NN2   (2 * LATD)    // 256

// ---------------- scratch (fp16 copies) ----------------
__device__ __align__(1024) __half g_Ahi[(size_t)B_DIM * KK1];
__device__ __align__(1024) __half g_W1hi[(size_t)NN1 * KK1];
__device__ __align__(1024) __half g_Hhi[(size_t)B_DIM * KK2];
__device__ __align__(1024) __half g_W2hi[(size_t)NN2 * KK2];

// ---------------- PTX helpers ----------------
__device__ __forceinline__ uint32_t smem_u32(const void* p) {
    uint32_t a;
    asm("{ .reg .u64 t; cvta.to.shared.u64 t, %1; cvt.u32.u64 %0, t; }" : "=r"(a) : "l"(p));
    return a;
}
__device__ __forceinline__ void cp16(uint32_t s, const void* g) {
    asm volatile("cp.async.cg.shared.global [%0], [%1], 16;" :: "r"(s), "l"(g));
}
__device__ __forceinline__ void cp_commit() { asm volatile("cp.async.commit_group;" ::: "memory"); }
__device__ __forceinline__ void cp_wait1()  { asm volatile("cp.async.wait_group 1;" ::: "memory"); }
__device__ __forceinline__ void cp_wait0()  { asm volatile("cp.async.wait_group 0;" ::: "memory"); }

__device__ __forceinline__ void ldsm_x4(uint32_t& r0, uint32_t& r1, uint32_t& r2, uint32_t& r3,
                                        uint32_t addr) {
    asm volatile("ldmatrix.sync.aligned.m8n8.x4.shared.b16 {%0,%1,%2,%3}, [%4];"
                 : "=r"(r0), "=r"(r1), "=r"(r2), "=r"(r3) : "r"(addr));
}
__device__ __forceinline__ void mma_fp16(float* c, const uint32_t* a, const uint32_t* b) {
    asm volatile(
        "mma.sync.aligned.m16n8k16.row.col.f32.f16.f16.f32 "
        "{%0,%1,%2,%3}, {%4,%5,%6,%7}, {%8,%9}, {%0,%1,%2,%3};"
        : "+f"(c[0]), "+f"(c[1]), "+f"(c[2]), "+f"(c[3])
        : "r"(a[0]), "r"(a[1]), "r"(a[2]), "r"(a[3]), "r"(b[0]), "r"(b[1]));
}
__device__ __forceinline__ uint32_t swz(uint32_t off) { return off ^ ((off >> 3) & 0x70); }

// ---------------- merged prepass: fp32 -> fp16, MLP=4, u32 index math ----------------
__device__ __forceinline__ void hi_store4(__half* hp, float4 v) {
    union { __half b[4]; uint2 u; } H;
    H.b[0] = __float2half_rn(v.x); H.b[1] = __float2half_rn(v.y);
    H.b[2] = __float2half_rn(v.z); H.b[3] = __float2half_rn(v.w);
    *(uint2*)hp = H.u;
}

#define N_A   ((uint32_t)((size_t)B_DIM * KK1 / 4))   // 4,718,592
#define N_W1  ((uint32_t)((size_t)NN1 * KK1 / 4))     // 1,179,648
#define N_W2  ((uint32_t)((size_t)NN2 * KK2 / 4))     //   131,072
#define N_TOT (N_A + N_W1 + N_W2)                     // 6,029,312
#define PRE_ILP 4

__global__ void k_prepass(const float* __restrict__ x, const float* __restrict__ h,
                          const float* __restrict__ W1, const float* __restrict__ W2) {
    const uint32_t i0 = blockIdx.x * blockDim.x + threadIdx.x;
    const uint32_t S  = gridDim.x * blockDim.x;

    float4 v[PRE_ILP];
    uint32_t idx[PRE_ILP];
#pragma unroll
    for (int it = 0; it < PRE_ILP; ++it) {
        uint32_t i = i0 + (uint32_t)it * S;
        idx[it] = i;
        if (i < N_A) {
            uint32_t row = i / 576u;            // KK1/4 = 576; u32 magic-mul division
            uint32_t col = (i - row * 576u) * 4u;
            v[it] = (col < OBS) ? *(const float4*)(x + (size_t)row * OBS + col)
                                : *(const float4*)(h + (size_t)row * NHD + (col - OBS));
        } else if (i < N_A + N_W1) {
            v[it] = *(const float4*)(W1 + (size_t)(i - N_A) * 4);
        } else if (i < N_TOT) {
            v[it] = *(const float4*)(W2 + (size_t)(i - N_A - N_W1) * 4);
        }
    }
#pragma unroll
    for (int it = 0; it < PRE_ILP; ++it) {
        uint32_t i = idx[it];
        if (i < N_A)                 hi_store4(g_Ahi + (size_t)i * 4, v[it]);
        else if (i < N_A + N_W1)     hi_store4(g_W1hi + (size_t)(i - N_A) * 4, v[it]);
        else if (i < N_TOT)          hi_store4(g_W2hi + (size_t)(i - N_A - N_W1) * 4, v[it]);
    }
}

// ---------------- tile loader: ROWS x 128B, SW128 swizzled, cp.async ----------------
template<int ROWS, int NTHR>
__device__ __forceinline__ void load_tile(uint32_t sdst, const __half* __restrict__ g,
                                          size_t row0, int ld, int kc, int tid) {
#pragma unroll
    for (int i = 0; i < ROWS * 8 / NTHR; ++i) {
        int op = i * NTHR + tid;
        int r = op >> 3;
        int c = (op & 7) << 4;
        const char* gp = (const char*)(g + (row0 + r) * (size_t)ld + kc) + c;
        cp16(sdst + swz((uint32_t)(r * 128 + c)), gp);
    }
}

// ================= GEMM1: 1-term, CTA 128x128, 8 warps (32x64 each), 3-stage =================
// stage = Ahi@0 (16K) + Bhi@16K (16K) = 32KB; 3 stages = 96KB; 2 CTAs/SM
__global__ __launch_bounds__(256, 2)
void g1_gemm(const float* __restrict__ bias, float* __restrict__ C) {
    constexpr int NTILES = KK1 / 64;   // 36
    constexpr int STAGE  = 32768;

    extern __shared__ unsigned char smem[];
    const uint32_t sb0 = smem_u32(smem);

    const int tid  = threadIdx.x;
    const int lane = tid & 31;
    const int wid  = tid >> 5;
    const int wm   = wid & 3;    // 4 warps along M -> 32 rows each
    const int wn   = wid >> 2;   // 2 warps along N -> 64 cols each
    const size_t m0 = (size_t)blockIdx.y * 128;
    const size_t n0 = (size_t)blockIdx.x * 128;

    float acc[2][8][4];
#pragma unroll
    for (int mt = 0; mt < 2; ++mt)
#pragma unroll
        for (int nt = 0; nt < 8; ++nt)
#pragma unroll
            for (int j = 0; j < 4; ++j) acc[mt][nt][j] = 0.0f;

    const uint32_t a_off0 = (uint32_t)((wm * 32 + (lane & 15)) * 128 + (lane >> 4) * 16);
    const uint32_t b_off0 = (uint32_t)((wn * 64 + (lane & 15)) * 128 + (lane >> 4) * 16);
    uint32_t asw[2], bsw[4];
#pragma unroll
    for (int mt = 0; mt < 2; ++mt) asw[mt] = swz(a_off0 + mt * 2048);
#pragma unroll
    for (int p = 0; p < 4; ++p) bsw[p] = swz(b_off0 + p * 2048);

    // prologue: stages 0,1
#pragma unroll
    for (int s = 0; s < 2; ++s) {
        uint32_t sb = sb0 + s * STAGE;
        load_tile<128, 256>(sb,         g_Ahi,  m0, KK1, s * 64, tid);
        load_tile<128, 256>(sb + 16384, g_W1hi, n0, KK1, s * 64, tid);
        cp_commit();
    }

    int sc = 0, sl = 2;
    for (int t = 0; t < NTILES; ++t) {
        cp_wait1();
        __syncthreads();

        // issue loads for t+2 into buffer finished two tiles ago
        if (t + 2 < NTILES) {
            uint32_t lb = sb0 + sl * STAGE;
            int kc = (t + 2) * 64;
            load_tile<128, 256>(lb,         g_Ahi,  m0, KK1, kc, tid);
            load_tile<128, 256>(lb + 16384, g_W1hi, n0, KK1, kc, tid);
        }
        cp_commit();

        const uint32_t sbA = sb0 + sc * STAGE;
        const uint32_t sbB = sbA + 16384;
#pragma unroll
        for (int ks = 0; ks < 4; ++ks) {
            const uint32_t kb = (uint32_t)(ks * 32);
            uint32_t ah[2][4];
#pragma unroll
            for (int mt = 0; mt < 2; ++mt)
                ldsm_x4(ah[mt][0], ah[mt][1], ah[mt][2], ah[mt][3], sbA + (asw[mt] ^ kb));
            uint32_t bh[8][2];
#pragma unroll
            for (int p = 0; p < 4; ++p) {
                uint32_t r0, r1, r2, r3;
                ldsm_x4(r0, r1, r2, r3, sbB + (bsw[p] ^ kb));
                bh[p * 2][0] = r0; bh[p * 2][1] = r2;
                bh[p * 2 + 1][0] = r1; bh[p * 2 + 1][1] = r3;
            }
#pragma unroll
            for (int mt = 0; mt < 2; ++mt)
#pragma unroll
                for (int nt = 0; nt < 8; ++nt)
                    mma_fp16(acc[mt][nt], ah[mt], bh[nt]);
        }
        sc = (sc == 2) ? 0 : sc + 1;
        sl = (sl == 2) ? 0 : sl + 1;
    }

    // epilogue: bias + tanh + fp32 store + fp16 copy for GEMM2
#pragma unroll
    for (int mt = 0; mt < 2; ++mt) {
        const size_t gr0 = m0 + wm * 32 + mt * 16 + (lane >> 2);
#pragma unroll
        for (int nt = 0; nt < 8; ++nt) {
            const size_t n = n0 + wn * 64 + nt * 8 + (lane & 3) * 2;
            const float bv0 = bias[n], bv1 = bias[n + 1];
#pragma unroll
            for (int hlf = 0; hlf < 2; ++hlf) {
                const size_t r = gr0 + hlf * 8;
                float v0 = tanhf(acc[mt][nt][hlf * 2 + 0] + bv0);
                float v1 = tanhf(acc[mt][nt][hlf * 2 + 1] + bv1);
                *(float2*)(C + r * (size_t)NN1 + n) = make_float2(v0, v1);
                union { __half b[2]; uint32_t u; } Hp;
                Hp.b[0] = __float2half_rn(v0);
                Hp.b[1] = __float2half_rn(v1);
                *(uint32_t*)(g_Hhi + r * (size_t)KK2 + n) = Hp.u;
            }
        }
    }
}

// ================= GEMM2: 1-term, CTA 128x64, 8 warps (32x32 each), 2-stage (R8 proven) =========
// stage = Hhi@0 (16K) + W2hi@16K (8K) = 24KB; 2 stages = 48KB; 2 CTAs/SM
__global__ __launch_bounds__(256, 2)
void g2_gemm(const float* __restrict__ bias, float* __restrict__ C) {
    constexpr int NTILES = KK2 / 64;   // 32
    constexpr int STAGE  = 24576;

    extern __shared__ unsigned char smem[];
    const uint32_t sb0 = smem_u32(smem);

    const int tid  = threadIdx.x;
    const int lane = tid & 31;
    const int wid  = tid >> 5;
    const int wm   = wid & 3;    // 4 warps along M -> 32 rows each
    const int wn   = wid >> 2;   // 2 warps along N -> 32 cols each
    const size_t m0 = (size_t)blockIdx.y * 128;
    const size_t n0 = (size_t)blockIdx.x * 64;

    float acc[2][4][4];
#pragma unroll
    for (int mt = 0; mt < 2; ++mt)
#pragma unroll
        for (int nt = 0; nt < 4; ++nt)
#pragma unroll
            for (int j = 0; j < 4; ++j) acc[mt][nt][j] = 0.0f;

    const uint32_t a_off0 = (uint32_t)((wm * 32 + (lane & 15)) * 128 + (lane >> 4) * 16);
    const uint32_t b_off0 = (uint32_t)((wn * 32 + (lane & 15)) * 128 + (lane >> 4) * 16);
    uint32_t asw[2], bsw[2];
#pragma unroll
    for (int mt = 0; mt < 2; ++mt) asw[mt] = swz(a_off0 + mt * 2048);
#pragma unroll
    for (int p = 0; p < 2; ++p) bsw[p] = swz(b_off0 + p * 2048);

#pragma unroll
    for (int s = 0; s < 2; ++s) {
        uint32_t sb = sb0 + s * STAGE;
        int kc = s * 64;
        load_tile<128, 256>(sb,         g_Hhi,  m0, KK2, kc, tid);
        load_tile<64,  256>(sb + 16384, g_W2hi, n0, KK2, kc, tid);
        cp_commit();
    }

    for (int t = 0; t < NTILES; ++t) {
        if (t + 1 < NTILES) cp_wait1(); else cp_wait0();
        __syncthreads();

        const uint32_t sb = sb0 + (t & 1) * STAGE;
#pragma unroll
        for (int ks = 0; ks < 4; ++ks) {
            const uint32_t kb = (uint32_t)(ks * 32);
            uint32_t ah[2][4];
#pragma unroll
            for (int mt = 0; mt < 2; ++mt)
                ldsm_x4(ah[mt][0], ah[mt][1], ah[mt][2], ah[mt][3], sb + (asw[mt] ^ kb));
            uint32_t bh[4][2];
#pragma unroll
            for (int p = 0; p < 2; ++p) {
                uint32_t r0, r1, r2, r3;
                ldsm_x4(r0, r1, r2, r3, sb + 16384 + (bsw[p] ^ kb));
                bh[p * 2][0] = r0; bh[p * 2][1] = r2;
                bh[p * 2 + 1][0] = r1; bh[p * 2 + 1][1] = r3;
            }
#pragma unroll
            for (int mt = 0; mt < 2; ++mt)
#pragma unroll
                for (int nt = 0; nt < 4; ++nt)
                    mma_fp16(acc[mt][nt], ah[mt], bh[nt]);
        }
        __syncthreads();

        if (t + 2 < NTILES) {
            uint32_t lb = sb0 + (t & 1) * STAGE;
            int kc = (t + 2) * 64;
            load_tile<128, 256>(lb,         g_Hhi,  m0, KK2, kc, tid);
            load_tile<64,  256>(lb + 16384, g_W2hi, n0, KK2, kc, tid);
        }
        cp_commit();
    }

#pragma unroll
    for (int mt = 0; mt < 2; ++mt) {
        const size_t gr0 = m0 + wm * 32 + mt * 16 + (lane >> 2);
#pragma unroll
        for (int nt = 0; nt < 4; ++nt) {
            const size_t n = n0 + wn * 32 + nt * 8 + (lane & 3) * 2;
            const float bv0 = bias[n], bv1 = bias[n + 1];
#pragma unroll
            for (int hlf = 0; hlf < 2; ++hlf) {
                const size_t r = gr0 + hlf * 8;
                float v0 = acc[mt][nt][hlf * 2 + 0] + bv0;
                float v1 = acc[mt][nt][hlf * 2 + 1] + bv1;
                *(float2*)(C + r * (size_t)NN2 + n) = make_float2(v0, v1);
            }
        }
    }
}

// ---------------- launch ----------------
extern "C" void kernel_launch(void* const* d_in, const int* in_sizes, int n_in,
                              void* d_out, int out_size) {
    const float* x  = (const float*)d_in[0];
    const float* h  = (const float*)d_in[1];
    const float* W1 = (const float*)d_in[2];
    const float* b1 = (const float*)d_in[3];
    const float* W2 = (const float*)d_in[4];
    const float* b2 = (const float*)d_in[5];

    float* out  = (float*)d_out;                 // [8192, 256]
    float* hnew = out + (size_t)B_DIM * NN2;     // [8192, 2048]

    const int SMEM1 = 3 * 32768;  // 96 KB -> 2 CTAs/SM
    const int SMEM2 = 2 * 24576;  // 48 KB -> 2 CTAs/SM
    cudaFuncSetAttribute(g1_gemm, cudaFuncAttributeMaxDynamicSharedMemorySize, SMEM1);
    cudaFuncSetAttribute(g2_gemm, cudaFuncAttributeMaxDynamicSharedMemorySize, SMEM2);

    const unsigned preBlocks = (N_TOT + 256 * PRE_ILP - 1) / (256 * PRE_ILP);
    k_prepass<<<preBlocks, 256>>>(x, h, W1, W2);

    g1_gemm<<<dim3(NN1 / 128, B_DIM / 128), 256, SMEM1>>>(b1, hnew);
    g2_gemm<<<dim3(NN2 / 64,  B_DIM / 128), 256, SMEM2>>>(b2, out);
}